// round 17
// baseline (speedup 1.0000x reference)
#include <cuda_runtime.h>
#include <cstdint>

#define BATCH  8192
#define DCONT  1024
#define VCAT   10000
#define VEC    2500          // float4s per categorical row
#define FULL   0xffffffffu
#define NWARP  4
#define NCHUNK 20            // 2KB chunks per row (last = 1088B)
#define CHUNKB 2048
#define NSTAGE 4
#define NSLOT  (2 * NCHUNK)  // 40 slots: slot s = (row s&1, chunk s>>1)

__device__ __forceinline__ void mbar_init(unsigned mbar, unsigned cnt) {
    asm volatile("mbarrier.init.shared.b64 [%0], %1;" :: "r"(mbar), "r"(cnt) : "memory");
}
__device__ __forceinline__ void mbar_expect_tx(unsigned mbar, unsigned bytes) {
    asm volatile("mbarrier.arrive.expect_tx.shared.b64 _, [%0], %1;"
                 :: "r"(mbar), "r"(bytes) : "memory");
}
__device__ __forceinline__ void mbar_wait(unsigned mbar, unsigned parity) {
    asm volatile(
        "{\n\t.reg .pred P;\n"
        "W_%=:\n\t"
        "mbarrier.try_wait.parity.acquire.cta.shared::cta.b64 P, [%0], %1;\n\t"
        "@!P bra W_%=;\n\t"
        "}" :: "r"(mbar), "r"(parity) : "memory");
}
__device__ __forceinline__ void bulk_ld(unsigned dst, const void* src,
                                        unsigned bytes, unsigned mbar) {
    asm volatile(
        "cp.async.bulk.shared::cluster.global.mbarrier::complete_tx::bytes "
        "[%0], [%1], %2, [%3];"
        :: "r"(dst), "l"(src), "r"(bytes), "r"(mbar) : "memory");
}

// Scan one staged chunk; rare warp-uniform walk gathers W_cat rows
// (broadcast c-quarter load, add predicated on g==0). Proven in R10.
__device__ __forceinline__ void scan_stage(const char* stage, int chunk,
                                           const float4* __restrict__ Wcat4,
                                           float4& acc, int& cnt,
                                           int lane, int g, int c4, bool tail) {
    const uint4* sp = reinterpret_cast<const uint4*>(stage);
    uint4 v0 = sp[lane];
    uint4 v1 = sp[lane + 32];
    uint4 v2 = sp[lane + 64];
    uint4 v3 = sp[lane + 96];
    if (tail) {                                // chunk 19: 68 valid vectors
        const uint4 z = make_uint4(0u, 0u, 0u, 0u);
        if (lane >= 4) v2 = z;
        v3 = z;
    }
    unsigned m =
          (v0.x ? 0x0001u : 0u) | (v0.y ? 0x0002u : 0u)
        | (v0.z ? 0x0004u : 0u) | (v0.w ? 0x0008u : 0u)
        | (v1.x ? 0x0010u : 0u) | (v1.y ? 0x0020u : 0u)
        | (v1.z ? 0x0040u : 0u) | (v1.w ? 0x0080u : 0u)
        | (v2.x ? 0x0100u : 0u) | (v2.y ? 0x0200u : 0u)
        | (v2.z ? 0x0400u : 0u) | (v2.w ? 0x0800u : 0u)
        | (v3.x ? 0x1000u : 0u) | (v3.y ? 0x2000u : 0u)
        | (v3.z ? 0x4000u : 0u) | (v3.w ? 0x8000u : 0u);
    cnt += __popc(m);
    unsigned bal = __ballot_sync(FULL, m != 0u);
    while (bal) {                              // ~0.6 sources per chunk
        int src = __ffs(bal) - 1;
        bal &= bal - 1;
        unsigned sm = __shfl_sync(FULL, m, src);
        int vb = chunk * 128 + src;
        #pragma unroll
        for (int j = 0; j < 4; j++) {
            unsigned mj = (sm >> (4 * j)) & 0xfu;
            if (mj) {
                int colb = (vb + j * 32) * 4;
                #pragma unroll
                for (int k = 0; k < 4; k++) {
                    if (mj & (1u << k)) {
                        float4 w = __ldg(Wcat4 + (size_t)(colb + k) * 4 + c4);
                        if (g == 0) { acc.x += w.x; acc.y += w.y;
                                      acc.z += w.z; acc.w += w.w; }
                    }
                }
            }
        }
    }
}

__global__ void __launch_bounds__(128, 7)
spfl_kernel(const float* __restrict__ xcont,
            const float* __restrict__ xcat,
            const float* __restrict__ Wc,
            const float* __restrict__ Wcat,
            const float* __restrict__ bias,
            float* __restrict__ out) {
    __shared__ __align__(128) char buf[NWARP][NSTAGE][CHUNKB];   // 32 KB
    __shared__ __align__(8) unsigned long long mbar[NWARP][NSTAGE];

    const int wid  = threadIdx.x >> 5;
    const int lane = threadIdx.x & 31;
    const int g  = lane >> 2;
    const int c4 = lane & 3;
    const int warp = blockIdx.x * NWARP + wid;
    const int row0 = warp * 2;                 // exact grid: no bounds check

    const uint4*  __restrict__ xr0   = reinterpret_cast<const uint4*>(xcat) + (size_t)row0 * VEC;
    const uint4*  __restrict__ xr1   = xr0 + VEC;
    const float4* __restrict__ Wcat4 = reinterpret_cast<const float4*>(Wcat);
    const float4* __restrict__ Wc4   = reinterpret_cast<const float4*>(Wc);

    const char* wbuf = &buf[wid][0][0];
    unsigned sbuf = (unsigned)__cvta_generic_to_shared(wbuf);
    unsigned sbar = (unsigned)__cvta_generic_to_shared(&mbar[wid][0]);

    if (lane == 0) {
        #pragma unroll
        for (int k = 0; k < NSTAGE; k++) mbar_init(sbar + 8u * k, 1);
        asm volatile("fence.proxy.async.shared::cta;" ::: "memory");
    }
    __syncwarp();

    float4 acc0 = make_float4(0.f, 0.f, 0.f, 0.f);
    float4 acc1 = make_float4(0.f, 0.f, 0.f, 0.f);
    int cnt0 = 0, cnt1 = 0;

    // Issue slot s: expect_tx + 1D bulk copy into stage s&3 (lane 0 only).
    #define ISSUE(s)                                                         \
        do { int _s = (s);                                                   \
             if (lane == 0 && _s < NSLOT) {                                  \
                 int _ch = _s >> 1;                                          \
                 const uint4* _src = ((_s & 1) ? xr1 : xr0) + _ch * 128;     \
                 unsigned _bytes = (_ch == NCHUNK - 1) ? 1088u : 2048u;      \
                 unsigned _bar = sbar + 8u * (unsigned)(_s & 3);             \
                 mbar_expect_tx(_bar, _bytes);                               \
                 bulk_ld(sbuf + (unsigned)((_s & 3) * CHUNKB), _src, _bytes, _bar); \
             } } while (0)

    ISSUE(0); ISSUE(1); ISSUE(2);              // prologue: 3 slots in flight

    #pragma unroll 1
    for (int ch = 0; ch < NCHUNK; ch++) {
        const bool tail = (ch == NCHUNK - 1);
        int s0 = 2 * ch, s1 = 2 * ch + 1;
        // row0 slot: keep 3 in flight, wait, scan
        ISSUE(s0 + 3);
        mbar_wait(sbar + 8u * (unsigned)(s0 & 3), (unsigned)((s0 >> 2) & 1));
        scan_stage(wbuf + (s0 & 3) * CHUNKB, ch, Wcat4, acc0, cnt0, lane, g, c4, tail);
        // row1 slot
        ISSUE(s1 + 3);
        mbar_wait(sbar + 8u * (unsigned)(s1 & 3), (unsigned)((s1 >> 2) & 1));
        scan_stage(wbuf + (s1 & 3) * CHUNKB, ch, Wcat4, acc1, cnt1, lane, g, c4, tail);
    }
    #undef ISSUE

    // ---- continuous branch: proven c/g layout (512B-contiguous W loads) ----
    const float* __restrict__ xc0 = xcont + (size_t)row0 * DCONT;
    const float* __restrict__ xc1 = xc0 + DCONT;
    #pragma unroll 1
    for (int jb = 0; jb < DCONT; jb += 32) {
        float x0 = __ldg(xc0 + jb + lane);
        float x1 = __ldg(xc1 + jb + lane);
        #pragma unroll
        for (int s = 0; s < 4; s++) {
            int jl = s * 8 + g;
            float4 w = __ldg(Wc4 + (size_t)(jb + jl) * 4 + c4);
            float a0 = __shfl_sync(FULL, x0, jl);
            float a1 = __shfl_sync(FULL, x1, jl);
            acc0.x += a0 * w.x; acc0.y += a0 * w.y; acc0.z += a0 * w.z; acc0.w += a0 * w.w;
            acc1.x += a1 * w.x; acc1.y += a1 * w.y; acc1.z += a1 * w.z; acc1.w += a1 * w.w;
        }
    }

    // ---- reduce acc over g (offsets 4,8,16); counts over all lanes ----
    #pragma unroll
    for (int off = 4; off <= 16; off <<= 1) {
        acc0.x += __shfl_xor_sync(FULL, acc0.x, off);
        acc0.y += __shfl_xor_sync(FULL, acc0.y, off);
        acc0.z += __shfl_xor_sync(FULL, acc0.z, off);
        acc0.w += __shfl_xor_sync(FULL, acc0.w, off);
        acc1.x += __shfl_xor_sync(FULL, acc1.x, off);
        acc1.y += __shfl_xor_sync(FULL, acc1.y, off);
        acc1.z += __shfl_xor_sync(FULL, acc1.z, off);
        acc1.w += __shfl_xor_sync(FULL, acc1.w, off);
    }
    #pragma unroll
    for (int off = 1; off <= 16; off <<= 1) {
        cnt0 += __shfl_xor_sync(FULL, cnt0, off);
        cnt1 += __shfl_xor_sync(FULL, cnt1, off);
    }

    if (lane < 4) {   // g == 0, quarter c4 == lane
        float4 b4 = __ldg(reinterpret_cast<const float4*>(bias) + lane);
        float f0 = (float)(DCONT + cnt0);
        float f1 = (float)(DCONT + cnt1);
        float4 o0, o1;
        o0.x = acc0.x + f0 * b4.x; o0.y = acc0.y + f0 * b4.y;
        o0.z = acc0.z + f0 * b4.z; o0.w = acc0.w + f0 * b4.w;
        o1.x = acc1.x + f1 * b4.x; o1.y = acc1.y + f1 * b4.y;
        o1.z = acc1.z + f1 * b4.z; o1.w = acc1.w + f1 * b4.w;
        reinterpret_cast<float4*>(out)[(size_t)row0 * 4 + lane]       = o0;
        reinterpret_cast<float4*>(out)[(size_t)(row0 + 1) * 4 + lane] = o1;
    }
}

extern "C" void kernel_launch(void* const* d_in, const int* in_sizes, int n_in,
                              void* d_out, int out_size) {
    const float* xcont = (const float*)d_in[0];   // [8192, 1024]
    const float* xcat  = (const float*)d_in[1];   // [8192, 10000]
    const float* Wc    = (const float*)d_in[2];   // [1024, 16]
    const float* Wcat  = (const float*)d_in[3];   // [10000, 16]
    const float* bias  = (const float*)d_in[4];   // [16]
    float* out = (float*)d_out;                   // [8192, 16]

    // 2 rows per warp, 4 warps per block -> 1024 blocks (single wave)
    dim3 grid(BATCH / (2 * NWARP));
    dim3 block(32 * NWARP);
    spfl_kernel<<<grid, block>>>(xcont, xcat, Wc, Wcat, bias, out);
}